// round 4
// baseline (speedup 1.0000x reference)
#include <cuda_runtime.h>
#include <math.h>
#include <stdint.h>

// Problem constants (fixed by the dataset)
#define NN      50000
#define EE_MAX  500000
#define ET_MAX  (NN + EE_MAX)
#define IND     384
#define HID1    1024   // 4 heads * 256
#define C1      256
#define H1      4
#define C2      128
#define NEG_SLOPE 0.2f

// ---------------- scratch (static device globals; no allocation) -------------
static __device__ __align__(16) float g_h0  [(size_t)NN * IND];
static __device__ __align__(16) float g_h1  [(size_t)NN * HID1];
static __device__ __align__(16) float g_o1  [(size_t)NN * HID1];  // layer-1 output (post ELU)
static __device__ __align__(16) float g_h2  [(size_t)NN * C2];

static __device__ __align__(16) float g_as1[NN * H1];
static __device__ __align__(16) float g_ad1[NN * H1];
static __device__ float g_as2[NN];
static __device__ float g_ad2[NN];

static __device__ __align__(16) float g_w1[(size_t)ET_MAX * H1];
static __device__ float g_w2[ET_MAX];

static __device__ int g_src[ET_MAX];
static __device__ int g_dst[ET_MAX];
static __device__ int g_deg[NN];
static __device__ int g_cursor[NN];
static __device__ int g_rowstart[NN + 1];
static __device__ int g_csr_src[ET_MAX];
static __device__ int g_is64;

// ---------------- mma helpers -------------------------------------------------
__device__ __forceinline__ uint32_t f2tf32(float f) {
    uint32_t u;
    asm("cvt.rna.tf32.f32 %0, %1;" : "=r"(u) : "f"(f));
    return u;
}

__device__ __forceinline__ void mma_tf32(float* c, const uint32_t* a, const uint32_t* b) {
    asm volatile(
        "mma.sync.aligned.m16n8k8.row.col.f32.tf32.tf32.f32 "
        "{%0,%1,%2,%3},{%4,%5,%6,%7},{%8,%9},{%0,%1,%2,%3};"
        : "+f"(c[0]), "+f"(c[1]), "+f"(c[2]), "+f"(c[3])
        : "r"(a[0]), "r"(a[1]), "r"(a[2]), "r"(a[3]), "r"(b[0]), "r"(b[1]));
}

// ---------------- small kernels -----------------------------------------------

__global__ void k_detect(const void* ei) {
    const unsigned int* u = (const unsigned int*)ei;
    int is64 = 1;
    #pragma unroll
    for (int i = 1; i < 16; i += 2)
        if (u[i] != 0u) is64 = 0;
    g_is64 = is64;
}

__global__ void k_prep(const void* ei, int E, int n) {
    int i = blockIdx.x * blockDim.x + threadIdx.x;
    int tot = E + n;
    if (i >= tot) return;
    int s, d;
    if (i < E) {
        if (g_is64) {
            const long long* p = (const long long*)ei;
            s = (int)p[i]; d = (int)p[E + i];
        } else {
            const int* p = (const int*)ei;
            s = p[i]; d = p[E + i];
        }
    } else {
        s = d = i - E;
    }
    g_src[i] = s; g_dst[i] = d;
}

__global__ void k_filli(int* p, int v, int count) {
    int i = blockIdx.x * blockDim.x + threadIdx.x;
    if (i < count) p[i] = v;
}

__global__ void k_zero2(float* a, float* b, int ca, int cb) {
    int i = blockIdx.x * blockDim.x + threadIdx.x;
    if (i < ca) a[i] = 0.f;
    if (i < cb) b[i] = 0.f;
}

__global__ void k_hist(int tot) {
    int i = blockIdx.x * blockDim.x + threadIdx.x;
    if (i < tot) atomicAdd(&g_deg[g_dst[i]], 1);
}

__global__ void __launch_bounds__(1024) k_scan(int n) {
    __shared__ int s_sum[1024];
    int t = threadIdx.x;
    const int CH = (NN + 1023) / 1024;   // 49
    int base = t * CH;
    int sum = 0;
    for (int i = 0; i < CH; i++) {
        int idx = base + i;
        if (idx < n) sum += g_deg[idx];
    }
    s_sum[t] = sum;
    __syncthreads();
    for (int o = 1; o < 1024; o <<= 1) {
        int v = 0;
        if (t >= o) v = s_sum[t - o];
        __syncthreads();
        if (t >= o) s_sum[t] += v;
        __syncthreads();
    }
    int run = (t > 0) ? s_sum[t - 1] : 0;
    for (int i = 0; i < CH; i++) {
        int idx = base + i;
        if (idx < n) { g_rowstart[idx] = run; run += g_deg[idx]; }
    }
    if (t == 1023) g_rowstart[n] = s_sum[1023];
}

__global__ void k_scatter(int tot) {
    int i = blockIdx.x * blockDim.x + threadIdx.x;
    if (i >= tot) return;
    int d = g_dst[i];
    int pos = atomicAdd(&g_cursor[d], 1);
    g_csr_src[g_rowstart[d] + pos] = g_src[i];
}

// ---------------- TF32 tensor-core GEMM (double-buffered, fused epilogues) ----
// C[M,N] = A[M,K] @ B[K,N], row-major. K%32==0, N%128==0.
// MODE 0: plain   MODE 1: encoder (C += na rank-2 + bias)
// MODE 2: alpha   (atomic partial dot(C-row, a_src/a_dst) per head)
template<int MODE>
__global__ void __launch_bounds__(256, 1) k_gemm(
    const float* __restrict__ A, const float* __restrict__ B,
    float* __restrict__ C, int M, int N, int K,
    const float* __restrict__ e0,   // MODE1: na      MODE2: a_src
    const float* __restrict__ e1,   // MODE1: encW+384*N  MODE2: a_dst
    const float* __restrict__ e2,   // MODE1: encb
    float* __restrict__ o0,         // MODE2: as_out
    float* __restrict__ o1,         // MODE2: ad_out
    int heads, int head_shift)
{
    __shared__ uint32_t As[2][128][36];
    __shared__ uint32_t Bs[2][32][136];

    int tid = threadIdx.x;
    int lane = tid & 31;
    int wid = tid >> 5;
    int g = lane >> 2;        // 0..7
    int t = lane & 3;         // 0..3
    int warp_m = wid & 3;     // 0..3 (32 rows each)
    int warp_n = wid >> 2;    // 0..1 (64 cols each)
    int row0 = blockIdx.y * 128;
    int col0 = blockIdx.x * 128;

    float acc[2][8][4];
    #pragma unroll
    for (int mt = 0; mt < 2; mt++)
        #pragma unroll
        for (int nt = 0; nt < 8; nt++)
            #pragma unroll
            for (int i = 0; i < 4; i++) acc[mt][nt][i] = 0.f;

    float4 pa[4], pb[4];
    int nIter = K >> 5;

    // prologue: tile 0 -> regs -> smem[0]
    #pragma unroll
    for (int i = 0; i < 4; i++) {
        int idx = tid + 256 * i;
        int ar = idx >> 3, ac4 = idx & 7;
        int gr = row0 + ar;
        pa[i] = (gr < M) ? *(const float4*)(A + (size_t)gr * K + ac4 * 4)
                         : make_float4(0.f, 0.f, 0.f, 0.f);
        int br = idx >> 5, bc4 = idx & 31;
        pb[i] = *(const float4*)(B + (size_t)br * N + col0 + bc4 * 4);
    }
    #pragma unroll
    for (int i = 0; i < 4; i++) {
        int idx = tid + 256 * i;
        int ar = idx >> 3, ac4 = idx & 7;
        *(uint4*)&As[0][ar][ac4 * 4] =
            make_uint4(f2tf32(pa[i].x), f2tf32(pa[i].y), f2tf32(pa[i].z), f2tf32(pa[i].w));
        int br = idx >> 5, bc4 = idx & 31;
        *(uint4*)&Bs[0][br][bc4 * 4] =
            make_uint4(f2tf32(pb[i].x), f2tf32(pb[i].y), f2tf32(pb[i].z), f2tf32(pb[i].w));
    }
    __syncthreads();

    for (int it = 0; it < nIter; it++) {
        int buf = it & 1;
        bool more = (it + 1 < nIter);
        if (more) {
            int k0g = (it + 1) * 32;
            #pragma unroll
            for (int i = 0; i < 4; i++) {
                int idx = tid + 256 * i;
                int ar = idx >> 3, ac4 = idx & 7;
                int gr = row0 + ar;
                pa[i] = (gr < M) ? *(const float4*)(A + (size_t)gr * K + k0g + ac4 * 4)
                                 : make_float4(0.f, 0.f, 0.f, 0.f);
                int br = idx >> 5, bc4 = idx & 31;
                pb[i] = *(const float4*)(B + (size_t)(k0g + br) * N + col0 + bc4 * 4);
            }
        }

        #pragma unroll
        for (int kk = 0; kk < 4; kk++) {
            int k0 = kk * 8;
            uint32_t af[2][4];
            #pragma unroll
            for (int mt = 0; mt < 2; mt++) {
                int mb = warp_m * 32 + mt * 16;
                af[mt][0] = As[buf][mb + g][k0 + t];
                af[mt][1] = As[buf][mb + g + 8][k0 + t];
                af[mt][2] = As[buf][mb + g][k0 + t + 4];
                af[mt][3] = As[buf][mb + g + 8][k0 + t + 4];
            }
            #pragma unroll
            for (int nt = 0; nt < 8; nt++) {
                uint32_t bf[2];
                int nb = warp_n * 64 + nt * 8;
                bf[0] = Bs[buf][k0 + t][nb + g];
                bf[1] = Bs[buf][k0 + t + 4][nb + g];
                mma_tf32(acc[0][nt], af[0], bf);
                mma_tf32(acc[1][nt], af[1], bf);
            }
        }

        if (more) {
            int nb = buf ^ 1;
            #pragma unroll
            for (int i = 0; i < 4; i++) {
                int idx = tid + 256 * i;
                int ar = idx >> 3, ac4 = idx & 7;
                *(uint4*)&As[nb][ar][ac4 * 4] =
                    make_uint4(f2tf32(pa[i].x), f2tf32(pa[i].y), f2tf32(pa[i].z), f2tf32(pa[i].w));
                int br = idx >> 5, bc4 = idx & 31;
                *(uint4*)&Bs[nb][br][bc4 * 4] =
                    make_uint4(f2tf32(pb[i].x), f2tf32(pb[i].y), f2tf32(pb[i].z), f2tf32(pb[i].w));
            }
        }
        __syncthreads();
    }

    // ---------------- epilogue ----------------
    #pragma unroll
    for (int mt = 0; mt < 2; mt++) {
        int rlo = row0 + warp_m * 32 + mt * 16 + g;
        int rhi = rlo + 8;
        float na_lo0 = 0.f, na_lo1 = 0.f, na_hi0 = 0.f, na_hi1 = 0.f;
        if (MODE == 1) {
            if (rlo < M) { na_lo0 = e0[rlo * 2]; na_lo1 = e0[rlo * 2 + 1]; }
            if (rhi < M) { na_hi0 = e0[rhi * 2]; na_hi1 = e0[rhi * 2 + 1]; }
        }
        float sa_lo = 0.f, sd_lo = 0.f, sa_hi = 0.f, sd_hi = 0.f;
        #pragma unroll
        for (int nt = 0; nt < 8; nt++) {
            int c = col0 + warp_n * 64 + nt * 8 + 2 * t;
            float v0 = acc[mt][nt][0], v1 = acc[mt][nt][1];
            float v2 = acc[mt][nt][2], v3 = acc[mt][nt][3];
            if (MODE == 1) {
                float w0x = e1[c], w0y = e1[c + 1];
                float w1x = e1[N + c], w1y = e1[N + c + 1];
                float bx = e2[c], by = e2[c + 1];
                v0 += na_lo0 * w0x + na_lo1 * w1x + bx;
                v1 += na_lo0 * w0y + na_lo1 * w1y + by;
                v2 += na_hi0 * w0x + na_hi1 * w1x + bx;
                v3 += na_hi0 * w0y + na_hi1 * w1y + by;
            }
            if (MODE == 2) {
                float asx = e0[c], asy = e0[c + 1];
                float adx = e1[c], ady = e1[c + 1];
                sa_lo += v0 * asx + v1 * asy;
                sd_lo += v0 * adx + v1 * ady;
                sa_hi += v2 * asx + v3 * asy;
                sd_hi += v2 * adx + v3 * ady;
            }
            if (rlo < M) *(float2*)(C + (size_t)rlo * N + c) = make_float2(v0, v1);
            if (rhi < M) *(float2*)(C + (size_t)rhi * N + c) = make_float2(v2, v3);
        }
        if (MODE == 2) {
            int head = col0 >> head_shift;
            if (rlo < M) {
                atomicAdd(&o0[rlo * heads + head], sa_lo);
                atomicAdd(&o1[rlo * heads + head], sd_lo);
            }
            if (rhi < M) {
                atomicAdd(&o0[rhi * heads + head], sa_hi);
                atomicAdd(&o1[rhi * heads + head], sd_hi);
            }
        }
    }
}

__device__ __forceinline__ float leaky(float e) {
    return (e >= 0.f) ? e : NEG_SLOPE * e;
}

// Fused layer-1 attention softmax + aggregation + bias + ELU.
// One 256-thread block per destination node.
__global__ void __launch_bounds__(256) k_attn_agg1(const float* __restrict__ b1) {
    int d = blockIdx.x;
    int t = threadIdx.x;
    int lane = t & 31;
    int beg = g_rowstart[d];
    int end = g_rowstart[d + 1];
    int deg = end - beg;

    __shared__ float s_inv[4];

    if (t < 32) {  // warp 0: softmax stats
        float4 ad = *(const float4*)(g_ad1 + d * 4);
        float m0 = -INFINITY, m1 = -INFINITY, m2 = -INFINITY, m3 = -INFINITY;
        for (int j = lane; j < deg; j += 32) {
            int s = g_csr_src[beg + j];
            float4 as = *(const float4*)(g_as1 + s * 4);
            float e0 = leaky(as.x + ad.x);
            float e1 = leaky(as.y + ad.y);
            float e2 = leaky(as.z + ad.z);
            float e3 = leaky(as.w + ad.w);
            *(float4*)(g_w1 + (size_t)(beg + j) * 4) = make_float4(e0, e1, e2, e3);
            m0 = fmaxf(m0, e0); m1 = fmaxf(m1, e1);
            m2 = fmaxf(m2, e2); m3 = fmaxf(m3, e3);
        }
        #pragma unroll
        for (int o = 16; o > 0; o >>= 1) {
            m0 = fmaxf(m0, __shfl_xor_sync(0xffffffffu, m0, o));
            m1 = fmaxf(m1, __shfl_xor_sync(0xffffffffu, m1, o));
            m2 = fmaxf(m2, __shfl_xor_sync(0xffffffffu, m2, o));
            m3 = fmaxf(m3, __shfl_xor_sync(0xffffffffu, m3, o));
        }
        float s0 = 0.f, s1 = 0.f, s2 = 0.f, s3 = 0.f;
        for (int j = lane; j < deg; j += 32) {
            float4 e = *(const float4*)(g_w1 + (size_t)(beg + j) * 4);
            float w0 = __expf(e.x - m0), w1 = __expf(e.y - m1);
            float w2 = __expf(e.z - m2), w3 = __expf(e.w - m3);
            *(float4*)(g_w1 + (size_t)(beg + j) * 4) = make_float4(w0, w1, w2, w3);
            s0 += w0; s1 += w1; s2 += w2; s3 += w3;
        }
        #pragma unroll
        for (int o = 16; o > 0; o >>= 1) {
            s0 += __shfl_xor_sync(0xffffffffu, s0, o);
            s1 += __shfl_xor_sync(0xffffffffu, s1, o);
            s2 += __shfl_xor_sync(0xffffffffu, s2, o);
            s3 += __shfl_xor_sync(0xffffffffu, s3, o);
        }
        if (lane == 0) {
            s_inv[0] = 1.f / (s0 + 1e-16f);
            s_inv[1] = 1.f / (s1 + 1e-16f);
            s_inv[2] = 1.f / (s2 + 1e-16f);
            s_inv[3] = 1.f / (s3 + 1e-16f);
        }
    }
    __syncthreads();

    float acc0 = 0.f, acc1 = 0.f, acc2 = 0.f, acc3 = 0.f;
    int j = 0;
    for (; j + 4 <= deg; j += 4) {
        int s0 = g_csr_src[beg + j];
        int s1 = g_csr_src[beg + j + 1];
        int s2 = g_csr_src[beg + j + 2];
        int s3 = g_csr_src[beg + j + 3];
        float4 w0 = *(const float4*)(g_w1 + (size_t)(beg + j) * 4);
        float4 w1 = *(const float4*)(g_w1 + (size_t)(beg + j + 1) * 4);
        float4 w2 = *(const float4*)(g_w1 + (size_t)(beg + j + 2) * 4);
        float4 w3 = *(const float4*)(g_w1 + (size_t)(beg + j + 3) * 4);
        const float* p0 = g_h1 + (size_t)s0 * HID1;
        const float* p1 = g_h1 + (size_t)s1 * HID1;
        const float* p2 = g_h1 + (size_t)s2 * HID1;
        const float* p3 = g_h1 + (size_t)s3 * HID1;
        acc0 += p0[t] * w0.x + p1[t] * w1.x + p2[t] * w2.x + p3[t] * w3.x;
        acc1 += p0[256 + t] * w0.y + p1[256 + t] * w1.y + p2[256 + t] * w2.y + p3[256 + t] * w3.y;
        acc2 += p0[512 + t] * w0.z + p1[512 + t] * w1.z + p2[512 + t] * w2.z + p3[512 + t] * w3.z;
        acc3 += p0[768 + t] * w0.w + p1[768 + t] * w1.w + p2[768 + t] * w2.w + p3[768 + t] * w3.w;
    }
    for (; j < deg; j++) {
        int s = g_csr_src[beg + j];
        float4 w = *(const float4*)(g_w1 + (size_t)(beg + j) * 4);
        const float* hs = g_h1 + (size_t)s * HID1;
        acc0 += hs[t] * w.x;
        acc1 += hs[256 + t] * w.y;
        acc2 += hs[512 + t] * w.z;
        acc3 += hs[768 + t] * w.w;
    }
    float v0 = acc0 * s_inv[0] + b1[t];
    float v1 = acc1 * s_inv[1] + b1[256 + t];
    float v2 = acc2 * s_inv[2] + b1[512 + t];
    float v3 = acc3 * s_inv[3] + b1[768 + t];
    float* od = g_o1 + (size_t)d * HID1;
    od[t]       = (v0 > 0.f) ? v0 : expm1f(v0);
    od[256 + t] = (v1 > 0.f) ? v1 : expm1f(v1);
    od[512 + t] = (v2 > 0.f) ? v2 : expm1f(v2);
    od[768 + t] = (v3 > 0.f) ? v3 : expm1f(v3);
}

// Fused layer-2 attention softmax + aggregation + bias -> out.
// One 128-thread block per destination node.
__global__ void __launch_bounds__(128) k_attn_agg2(const float* __restrict__ b2,
                                                   float* __restrict__ out) {
    int d = blockIdx.x;
    int t = threadIdx.x;
    int lane = t & 31;
    int beg = g_rowstart[d];
    int end = g_rowstart[d + 1];
    int deg = end - beg;

    __shared__ float s_inv;

    if (t < 32) {
        float ad = g_ad2[d];
        float m = -INFINITY;
        for (int j = lane; j < deg; j += 32) {
            int s = g_csr_src[beg + j];
            float e = leaky(g_as2[s] + ad);
            g_w2[beg + j] = e;
            m = fmaxf(m, e);
        }
        #pragma unroll
        for (int o = 16; o > 0; o >>= 1)
            m = fmaxf(m, __shfl_xor_sync(0xffffffffu, m, o));
        float sum = 0.f;
        for (int j = lane; j < deg; j += 32) {
            float w = __expf(g_w2[beg + j] - m);
            g_w2[beg + j] = w;
            sum += w;
        }
        #pragma unroll
        for (int o = 16; o > 0; o >>= 1)
            sum += __shfl_xor_sync(0xffffffffu, sum, o);
        if (lane == 0) s_inv = 1.f / (sum + 1e-16f);
    }
    __syncthreads();

    float acc = 0.f;
    int j = 0;
    for (; j + 4 <= deg; j += 4) {
        int s0 = g_csr_src[beg + j];
        int s1 = g_csr_src[beg + j + 1];
        int s2 = g_csr_src[beg + j + 2];
        int s3 = g_csr_src[beg + j + 3];
        float w0 = g_w2[beg + j], w1 = g_w2[beg + j + 1];
        float w2 = g_w2[beg + j + 2], w3 = g_w2[beg + j + 3];
        acc += g_h2[(size_t)s0 * C2 + t] * w0 + g_h2[(size_t)s1 * C2 + t] * w1
             + g_h2[(size_t)s2 * C2 + t] * w2 + g_h2[(size_t)s3 * C2 + t] * w3;
    }
    for (; j < deg; j++) {
        int s = g_csr_src[beg + j];
        acc += g_h2[(size_t)s * C2 + t] * g_w2[beg + j];
    }
    out[(size_t)d * C2 + t] = acc * s_inv + b2[t];
}

// ---------------- host launcher ----------------------------------------------
extern "C" void kernel_launch(void* const* d_in, const int* in_sizes, int n_in,
                              void* d_out, int out_size) {
    const float* x       = (const float*)d_in[0];
    const float* na      = (const float*)d_in[1];
    const void*  ei      = d_in[2];
    const float* encW    = (const float*)d_in[3];
    const float* encb    = (const float*)d_in[4];
    const float* W1      = (const float*)d_in[5];
    const float* a_src1  = (const float*)d_in[6];
    const float* a_dst1  = (const float*)d_in[7];
    const float* b1      = (const float*)d_in[8];
    const float* W2      = (const float*)d_in[9];
    const float* a_src2  = (const float*)d_in[10];
    const float* a_dst2  = (const float*)d_in[11];
    const float* b2      = (const float*)d_in[12];
    float* out = (float*)d_out;

    int n = in_sizes[0] / IND;
    int E = in_sizes[2] / 2;
    int tot = E + n;

    int *p_deg, *p_cursor;
    cudaGetSymbolAddress((void**)&p_deg, g_deg);
    cudaGetSymbolAddress((void**)&p_cursor, g_cursor);
    float *p_h0, *p_h1, *p_o1, *p_h2;
    cudaGetSymbolAddress((void**)&p_h0, g_h0);
    cudaGetSymbolAddress((void**)&p_h1, g_h1);
    cudaGetSymbolAddress((void**)&p_o1, g_o1);
    cudaGetSymbolAddress((void**)&p_h2, g_h2);
    float *p_as1, *p_ad1, *p_as2, *p_ad2;
    cudaGetSymbolAddress((void**)&p_as1, g_as1);
    cudaGetSymbolAddress((void**)&p_ad1, g_ad1);
    cudaGetSymbolAddress((void**)&p_as2, g_as2);
    cudaGetSymbolAddress((void**)&p_ad2, g_ad2);

    // launches 1-5 (CSR front half)
    k_detect<<<1, 1>>>(ei);
    k_prep<<<(tot + 255) / 256, 256>>>(ei, E, n);
    k_filli<<<(n + 255) / 256, 256>>>(p_deg, 0, n);
    k_filli<<<(n + 255) / 256, 256>>>(p_cursor, 0, n);
    k_hist<<<(tot + 255) / 256, 256>>>(tot);

    // launch 6: encoder GEMM with fused rank-2 + bias epilogue (ncu -s 5 lands here)
    {
        dim3 grid(IND / 128, (n + 127) / 128);
        k_gemm<1><<<grid, 256>>>(x, encW, p_h0, n, IND, IND,
                                 na, encW + (size_t)384 * IND, encb,
                                 nullptr, nullptr, 0, 0);
    }

    // CSR back half
    k_scan<<<1, 1024>>>(n);
    k_scatter<<<(tot + 255) / 256, 256>>>(tot);

    // ---- GAT layer 1: GEMM with fused alpha epilogue ----
    k_zero2<<<(n * H1 + 255) / 256, 256>>>(p_as1, p_ad1, n * H1, n * H1);
    {
        dim3 grid(HID1 / 128, (n + 127) / 128);
        k_gemm<2><<<grid, 256>>>(p_h0, W1, p_h1, n, HID1, IND,
                                 a_src1, a_dst1, nullptr,
                                 p_as1, p_ad1, H1, 8);
    }
    k_attn_agg1<<<n, 256>>>(b1);

    // ---- GAT layer 2: GEMM with fused alpha epilogue ----
    k_zero2<<<(n + 255) / 256, 256>>>(p_as2, p_ad2, n, n);
    {
        dim3 grid(C2 / 128, (n + 127) / 128);
        k_gemm<2><<<grid, 256>>>(p_o1, W2, p_h2, n, C2, HID1,
                                 a_src2, a_dst2, nullptr,
                                 p_as2, p_ad2, 1, 7);
    }
    k_attn_agg2<<<n, 128>>>(b2, out);
}

// round 5
// speedup vs baseline: 1.0245x; 1.0245x over previous
#include <cuda_runtime.h>
#include <math.h>
#include <stdint.h>

// Problem constants (fixed by the dataset)
#define NN      50000
#define EE_MAX  500000
#define ET_MAX  (NN + EE_MAX)
#define IND     384
#define HID1    1024   // 4 heads * 256
#define C1      256
#define H1      4
#define C2      128
#define NEG_SLOPE 0.2f

// ---------------- scratch (static device globals; no allocation) -------------
static __device__ __align__(16) float g_h0  [(size_t)NN * IND];
static __device__ __align__(16) float g_h1  [(size_t)NN * HID1];
static __device__ __align__(16) float g_o1  [(size_t)NN * HID1];  // layer-1 output (post ELU)
static __device__ __align__(16) float g_h2  [(size_t)NN * C2];

static __device__ __align__(16) float g_as1[NN * H1];
static __device__ __align__(16) float g_ad1[NN * H1];
static __device__ float g_as2[NN];
static __device__ float g_ad2[NN];

static __device__ __align__(16) float g_w1[(size_t)ET_MAX * H1];
static __device__ float g_w2[ET_MAX];

static __device__ int g_src[ET_MAX];
static __device__ int g_dst[ET_MAX];
static __device__ int g_deg[NN];
static __device__ int g_cursor[NN];
static __device__ int g_rowstart[NN + 1];
static __device__ int g_csr_src[ET_MAX];
static __device__ int g_is64;

// ---------------- mma helpers -------------------------------------------------
__device__ __forceinline__ uint32_t f2tf32(float f) {
    uint32_t u;
    asm("cvt.rna.tf32.f32 %0, %1;" : "=r"(u) : "f"(f));
    return u;
}

__device__ __forceinline__ void mma_tf32(float* c, const uint32_t* a, const uint32_t* b) {
    asm volatile(
        "mma.sync.aligned.m16n8k8.row.col.f32.tf32.tf32.f32 "
        "{%0,%1,%2,%3},{%4,%5,%6,%7},{%8,%9},{%0,%1,%2,%3};"
        : "+f"(c[0]), "+f"(c[1]), "+f"(c[2]), "+f"(c[3])
        : "r"(a[0]), "r"(a[1]), "r"(a[2]), "r"(a[3]), "r"(b[0]), "r"(b[1]));
}

// ---------------- small kernels -----------------------------------------------

__global__ void k_detect(const void* ei) {
    const unsigned int* u = (const unsigned int*)ei;
    int is64 = 1;
    #pragma unroll
    for (int i = 1; i < 16; i += 2)
        if (u[i] != 0u) is64 = 0;
    g_is64 = is64;
}

__global__ void k_prep(const void* ei, int E, int n) {
    int i = blockIdx.x * blockDim.x + threadIdx.x;
    int tot = E + n;
    if (i >= tot) return;
    int s, d;
    if (i < E) {
        if (g_is64) {
            const long long* p = (const long long*)ei;
            s = (int)p[i]; d = (int)p[E + i];
        } else {
            const int* p = (const int*)ei;
            s = p[i]; d = p[E + i];
        }
    } else {
        s = d = i - E;
    }
    g_src[i] = s; g_dst[i] = d;
}

__global__ void k_filli(int* p, int v, int count) {
    int i = blockIdx.x * blockDim.x + threadIdx.x;
    if (i < count) p[i] = v;
}

__global__ void k_zero2(float* a, float* b, int ca, int cb) {
    int i = blockIdx.x * blockDim.x + threadIdx.x;
    if (i < ca) a[i] = 0.f;
    if (i < cb) b[i] = 0.f;
}

__global__ void k_hist(int tot) {
    int i = blockIdx.x * blockDim.x + threadIdx.x;
    if (i < tot) atomicAdd(&g_deg[g_dst[i]], 1);
}

__global__ void __launch_bounds__(1024) k_scan(int n) {
    __shared__ int s_sum[1024];
    int t = threadIdx.x;
    const int CH = (NN + 1023) / 1024;   // 49
    int base = t * CH;
    int sum = 0;
    for (int i = 0; i < CH; i++) {
        int idx = base + i;
        if (idx < n) sum += g_deg[idx];
    }
    s_sum[t] = sum;
    __syncthreads();
    for (int o = 1; o < 1024; o <<= 1) {
        int v = 0;
        if (t >= o) v = s_sum[t - o];
        __syncthreads();
        if (t >= o) s_sum[t] += v;
        __syncthreads();
    }
    int run = (t > 0) ? s_sum[t - 1] : 0;
    for (int i = 0; i < CH; i++) {
        int idx = base + i;
        if (idx < n) { g_rowstart[idx] = run; run += g_deg[idx]; }
    }
    if (t == 1023) g_rowstart[n] = s_sum[1023];
}

__global__ void k_scatter(int tot) {
    int i = blockIdx.x * blockDim.x + threadIdx.x;
    if (i >= tot) return;
    int d = g_dst[i];
    int pos = atomicAdd(&g_cursor[d], 1);
    g_csr_src[g_rowstart[d] + pos] = g_src[i];
}

// ---------------- TF32 tensor-core GEMM (single-buffer, fused epilogues) ------
// C[M,N] = A[M,K] @ B[K,N], row-major. K%32==0, N%128==0.
// MODE 0: plain   MODE 1: encoder (C += na rank-2 + bias)
// MODE 2: alpha   (atomic partial dot(C-row, a_src/a_dst) per head)
template<int MODE>
__global__ void __launch_bounds__(256, 1) k_gemm(
    const float* __restrict__ A, const float* __restrict__ B,
    float* __restrict__ C, int M, int N, int K,
    const float* __restrict__ e0,   // MODE1: na          MODE2: a_src
    const float* __restrict__ e1,   // MODE1: encW+384*N  MODE2: a_dst
    const float* __restrict__ e2,   // MODE1: encb
    float* __restrict__ o0,         // MODE2: as_out
    float* __restrict__ o1,         // MODE2: ad_out
    int heads, int head_shift)
{
    __shared__ uint32_t As[128][36];
    __shared__ uint32_t Bs[32][136];

    int tid = threadIdx.x;
    int lane = tid & 31;
    int wid = tid >> 5;
    int g = lane >> 2;        // 0..7
    int t = lane & 3;         // 0..3
    int warp_m = wid & 3;     // 0..3 (32 rows each)
    int warp_n = wid >> 2;    // 0..1 (64 cols each)
    int row0 = blockIdx.y * 128;
    int col0 = blockIdx.x * 128;

    float acc[2][8][4];
    #pragma unroll
    for (int mt = 0; mt < 2; mt++)
        #pragma unroll
        for (int nt = 0; nt < 8; nt++)
            #pragma unroll
            for (int i = 0; i < 4; i++) acc[mt][nt][i] = 0.f;

    float4 pa[4], pb[4];
    int nIter = K >> 5;

    // prologue: load k-tile 0
    #pragma unroll
    for (int i = 0; i < 4; i++) {
        int idx = tid + 256 * i;
        int ar = idx >> 3, ac4 = idx & 7;
        int gr = row0 + ar;
        pa[i] = (gr < M) ? *(const float4*)(A + (size_t)gr * K + ac4 * 4)
                         : make_float4(0.f, 0.f, 0.f, 0.f);
        int br = idx >> 5, bc4 = idx & 31;
        pb[i] = *(const float4*)(B + (size_t)br * N + col0 + bc4 * 4);
    }
    #pragma unroll
    for (int i = 0; i < 4; i++) {
        int idx = tid + 256 * i;
        int ar = idx >> 3, ac4 = idx & 7;
        *(uint4*)&As[ar][ac4 * 4] =
            make_uint4(f2tf32(pa[i].x), f2tf32(pa[i].y), f2tf32(pa[i].z), f2tf32(pa[i].w));
        int br = idx >> 5, bc4 = idx & 31;
        *(uint4*)&Bs[br][bc4 * 4] =
            make_uint4(f2tf32(pb[i].x), f2tf32(pb[i].y), f2tf32(pb[i].z), f2tf32(pb[i].w));
    }
    __syncthreads();

    for (int it = 0; it < nIter; it++) {
        bool more = (it + 1 < nIter);
        if (more) {
            int k0g = (it + 1) * 32;
            #pragma unroll
            for (int i = 0; i < 4; i++) {
                int idx = tid + 256 * i;
                int ar = idx >> 3, ac4 = idx & 7;
                int gr = row0 + ar;
                pa[i] = (gr < M) ? *(const float4*)(A + (size_t)gr * K + k0g + ac4 * 4)
                                 : make_float4(0.f, 0.f, 0.f, 0.f);
                int br = idx >> 5, bc4 = idx & 31;
                pb[i] = *(const float4*)(B + (size_t)(k0g + br) * N + col0 + bc4 * 4);
            }
        }

        // compute on current smem tile
        #pragma unroll
        for (int kk = 0; kk < 4; kk++) {
            int k0 = kk * 8;
            uint32_t af[2][4];
            #pragma unroll
            for (int mt = 0; mt < 2; mt++) {
                int mb = warp_m * 32 + mt * 16;
                af[mt][0] = As[mb + g][k0 + t];
                af[mt][1] = As[mb + g + 8][k0 + t];
                af[mt][2] = As[mb + g][k0 + t + 4];
                af[mt][3] = As[mb + g + 8][k0 + t + 4];
            }
            #pragma unroll
            for (int nt = 0; nt < 8; nt++) {
                uint32_t bf[2];
                int nb = warp_n * 64 + nt * 8;
                bf[0] = Bs[k0 + t][nb + g];
                bf[1] = Bs[k0 + t + 4][nb + g];
                mma_tf32(acc[0][nt], af[0], bf);
                mma_tf32(acc[1][nt], af[1], bf);
            }
        }

        if (more) {
            __syncthreads();
            #pragma unroll
            for (int i = 0; i < 4; i++) {
                int idx = tid + 256 * i;
                int ar = idx >> 3, ac4 = idx & 7;
                *(uint4*)&As[ar][ac4 * 4] =
                    make_uint4(f2tf32(pa[i].x), f2tf32(pa[i].y), f2tf32(pa[i].z), f2tf32(pa[i].w));
                int br = idx >> 5, bc4 = idx & 31;
                *(uint4*)&Bs[br][bc4 * 4] =
                    make_uint4(f2tf32(pb[i].x), f2tf32(pb[i].y), f2tf32(pb[i].z), f2tf32(pb[i].w));
            }
            __syncthreads();
        }
    }

    // ---------------- epilogue ----------------
    #pragma unroll
    for (int mt = 0; mt < 2; mt++) {
        int rlo = row0 + warp_m * 32 + mt * 16 + g;
        int rhi = rlo + 8;
        float na_lo0 = 0.f, na_lo1 = 0.f, na_hi0 = 0.f, na_hi1 = 0.f;
        if (MODE == 1) {
            if (rlo < M) { na_lo0 = e0[rlo * 2]; na_lo1 = e0[rlo * 2 + 1]; }
            if (rhi < M) { na_hi0 = e0[rhi * 2]; na_hi1 = e0[rhi * 2 + 1]; }
        }
        float sa_lo = 0.f, sd_lo = 0.f, sa_hi = 0.f, sd_hi = 0.f;
        #pragma unroll
        for (int nt = 0; nt < 8; nt++) {
            int c = col0 + warp_n * 64 + nt * 8 + 2 * t;
            float v0 = acc[mt][nt][0], v1 = acc[mt][nt][1];
            float v2 = acc[mt][nt][2], v3 = acc[mt][nt][3];
            if (MODE == 1) {
                float w0x = e1[c], w0y = e1[c + 1];
                float w1x = e1[N + c], w1y = e1[N + c + 1];
                float bx = e2[c], by = e2[c + 1];
                v0 += na_lo0 * w0x + na_lo1 * w1x + bx;
                v1 += na_lo0 * w0y + na_lo1 * w1y + by;
                v2 += na_hi0 * w0x + na_hi1 * w1x + bx;
                v3 += na_hi0 * w0y + na_hi1 * w1y + by;
            }
            if (MODE == 2) {
                float asx = e0[c], asy = e0[c + 1];
                float adx = e1[c], ady = e1[c + 1];
                sa_lo += v0 * asx + v1 * asy;
                sd_lo += v0 * adx + v1 * ady;
                sa_hi += v2 * asx + v3 * asy;
                sd_hi += v2 * adx + v3 * ady;
            }
            if (rlo < M) *(float2*)(C + (size_t)rlo * N + c) = make_float2(v0, v1);
            if (rhi < M) *(float2*)(C + (size_t)rhi * N + c) = make_float2(v2, v3);
        }
        if (MODE == 2) {
            int head = col0 >> head_shift;
            if (rlo < M) {
                atomicAdd(&o0[rlo * heads + head], sa_lo);
                atomicAdd(&o1[rlo * heads + head], sd_lo);
            }
            if (rhi < M) {
                atomicAdd(&o0[rhi * heads + head], sa_hi);
                atomicAdd(&o1[rhi * heads + head], sd_hi);
            }
        }
    }
}

__device__ __forceinline__ float leaky(float e) {
    return (e >= 0.f) ? e : NEG_SLOPE * e;
}

// Fused layer-1 attention softmax + aggregation + bias + ELU.
// One 256-thread block per destination node.
__global__ void __launch_bounds__(256) k_attn_agg1(const float* __restrict__ b1) {
    int d = blockIdx.x;
    int t = threadIdx.x;
    int lane = t & 31;
    int beg = g_rowstart[d];
    int end = g_rowstart[d + 1];
    int deg = end - beg;

    __shared__ float s_inv[4];

    if (t < 32) {  // warp 0: softmax stats
        float4 ad = *(const float4*)(g_ad1 + d * 4);
        float m0 = -INFINITY, m1 = -INFINITY, m2 = -INFINITY, m3 = -INFINITY;
        for (int j = lane; j < deg; j += 32) {
            int s = g_csr_src[beg + j];
            float4 as = *(const float4*)(g_as1 + s * 4);
            float e0 = leaky(as.x + ad.x);
            float e1 = leaky(as.y + ad.y);
            float e2 = leaky(as.z + ad.z);
            float e3 = leaky(as.w + ad.w);
            *(float4*)(g_w1 + (size_t)(beg + j) * 4) = make_float4(e0, e1, e2, e3);
            m0 = fmaxf(m0, e0); m1 = fmaxf(m1, e1);
            m2 = fmaxf(m2, e2); m3 = fmaxf(m3, e3);
        }
        #pragma unroll
        for (int o = 16; o > 0; o >>= 1) {
            m0 = fmaxf(m0, __shfl_xor_sync(0xffffffffu, m0, o));
            m1 = fmaxf(m1, __shfl_xor_sync(0xffffffffu, m1, o));
            m2 = fmaxf(m2, __shfl_xor_sync(0xffffffffu, m2, o));
            m3 = fmaxf(m3, __shfl_xor_sync(0xffffffffu, m3, o));
        }
        float s0 = 0.f, s1 = 0.f, s2 = 0.f, s3 = 0.f;
        for (int j = lane; j < deg; j += 32) {
            float4 e = *(const float4*)(g_w1 + (size_t)(beg + j) * 4);
            float w0 = __expf(e.x - m0), w1 = __expf(e.y - m1);
            float w2 = __expf(e.z - m2), w3 = __expf(e.w - m3);
            *(float4*)(g_w1 + (size_t)(beg + j) * 4) = make_float4(w0, w1, w2, w3);
            s0 += w0; s1 += w1; s2 += w2; s3 += w3;
        }
        #pragma unroll
        for (int o = 16; o > 0; o >>= 1) {
            s0 += __shfl_xor_sync(0xffffffffu, s0, o);
            s1 += __shfl_xor_sync(0xffffffffu, s1, o);
            s2 += __shfl_xor_sync(0xffffffffu, s2, o);
            s3 += __shfl_xor_sync(0xffffffffu, s3, o);
        }
        if (lane == 0) {
            s_inv[0] = 1.f / (s0 + 1e-16f);
            s_inv[1] = 1.f / (s1 + 1e-16f);
            s_inv[2] = 1.f / (s2 + 1e-16f);
            s_inv[3] = 1.f / (s3 + 1e-16f);
        }
    }
    __syncthreads();

    float acc0 = 0.f, acc1 = 0.f, acc2 = 0.f, acc3 = 0.f;
    int j = 0;
    for (; j + 4 <= deg; j += 4) {
        int s0 = g_csr_src[beg + j];
        int s1 = g_csr_src[beg + j + 1];
        int s2 = g_csr_src[beg + j + 2];
        int s3 = g_csr_src[beg + j + 3];
        float4 w0 = *(const float4*)(g_w1 + (size_t)(beg + j) * 4);
        float4 w1 = *(const float4*)(g_w1 + (size_t)(beg + j + 1) * 4);
        float4 w2 = *(const float4*)(g_w1 + (size_t)(beg + j + 2) * 4);
        float4 w3 = *(const float4*)(g_w1 + (size_t)(beg + j + 3) * 4);
        const float* p0 = g_h1 + (size_t)s0 * HID1;
        const float* p1 = g_h1 + (size_t)s1 * HID1;
        const float* p2 = g_h1 + (size_t)s2 * HID1;
        const float* p3 = g_h1 + (size_t)s3 * HID1;
        acc0 += p0[t] * w0.x + p1[t] * w1.x + p2[t] * w2.x + p3[t] * w3.x;
        acc1 += p0[256 + t] * w0.y + p1[256 + t] * w1.y + p2[256 + t] * w2.y + p3[256 + t] * w3.y;
        acc2 += p0[512 + t] * w0.z + p1[512 + t] * w1.z + p2[512 + t] * w2.z + p3[512 + t] * w3.z;
        acc3 += p0[768 + t] * w0.w + p1[768 + t] * w1.w + p2[768 + t] * w2.w + p3[768 + t] * w3.w;
    }
    for (; j < deg; j++) {
        int s = g_csr_src[beg + j];
        float4 w = *(const float4*)(g_w1 + (size_t)(beg + j) * 4);
        const float* hs = g_h1 + (size_t)s * HID1;
        acc0 += hs[t] * w.x;
        acc1 += hs[256 + t] * w.y;
        acc2 += hs[512 + t] * w.z;
        acc3 += hs[768 + t] * w.w;
    }
    float v0 = acc0 * s_inv[0] + b1[t];
    float v1 = acc1 * s_inv[1] + b1[256 + t];
    float v2 = acc2 * s_inv[2] + b1[512 + t];
    float v3 = acc3 * s_inv[3] + b1[768 + t];
    float* od = g_o1 + (size_t)d * HID1;
    od[t]       = (v0 > 0.f) ? v0 : expm1f(v0);
    od[256 + t] = (v1 > 0.f) ? v1 : expm1f(v1);
    od[512 + t] = (v2 > 0.f) ? v2 : expm1f(v2);
    od[768 + t] = (v3 > 0.f) ? v3 : expm1f(v3);
}

// Fused layer-2 attention softmax + aggregation + bias -> out.
// One 128-thread block per destination node.
__global__ void __launch_bounds__(128) k_attn_agg2(const float* __restrict__ b2,
                                                   float* __restrict__ out) {
    int d = blockIdx.x;
    int t = threadIdx.x;
    int lane = t & 31;
    int beg = g_rowstart[d];
    int end = g_rowstart[d + 1];
    int deg = end - beg;

    __shared__ float s_inv;

    if (t < 32) {
        float ad = g_ad2[d];
        float m = -INFINITY;
        for (int j = lane; j < deg; j += 32) {
            int s = g_csr_src[beg + j];
            float e = leaky(g_as2[s] + ad);
            g_w2[beg + j] = e;
            m = fmaxf(m, e);
        }
        #pragma unroll
        for (int o = 16; o > 0; o >>= 1)
            m = fmaxf(m, __shfl_xor_sync(0xffffffffu, m, o));
        float sum = 0.f;
        for (int j = lane; j < deg; j += 32) {
            float w = __expf(g_w2[beg + j] - m);
            g_w2[beg + j] = w;
            sum += w;
        }
        #pragma unroll
        for (int o = 16; o > 0; o >>= 1)
            sum += __shfl_xor_sync(0xffffffffu, sum, o);
        if (lane == 0) s_inv = 1.f / (sum + 1e-16f);
    }
    __syncthreads();

    float acc = 0.f;
    int j = 0;
    for (; j + 4 <= deg; j += 4) {
        int s0 = g_csr_src[beg + j];
        int s1 = g_csr_src[beg + j + 1];
        int s2 = g_csr_src[beg + j + 2];
        int s3 = g_csr_src[beg + j + 3];
        float w0 = g_w2[beg + j], w1 = g_w2[beg + j + 1];
        float w2 = g_w2[beg + j + 2], w3 = g_w2[beg + j + 3];
        acc += g_h2[(size_t)s0 * C2 + t] * w0 + g_h2[(size_t)s1 * C2 + t] * w1
             + g_h2[(size_t)s2 * C2 + t] * w2 + g_h2[(size_t)s3 * C2 + t] * w3;
    }
    for (; j < deg; j++) {
        int s = g_csr_src[beg + j];
        acc += g_h2[(size_t)s * C2 + t] * g_w2[beg + j];
    }
    out[(size_t)d * C2 + t] = acc * s_inv + b2[t];
}

// ---------------- host launcher ----------------------------------------------
extern "C" void kernel_launch(void* const* d_in, const int* in_sizes, int n_in,
                              void* d_out, int out_size) {
    const float* x       = (const float*)d_in[0];
    const float* na      = (const float*)d_in[1];
    const void*  ei      = d_in[2];
    const float* encW    = (const float*)d_in[3];
    const float* encb    = (const float*)d_in[4];
    const float* W1      = (const float*)d_in[5];
    const float* a_src1  = (const float*)d_in[6];
    const float* a_dst1  = (const float*)d_in[7];
    const float* b1      = (const float*)d_in[8];
    const float* W2      = (const float*)d_in[9];
    const float* a_src2  = (const float*)d_in[10];
    const float* a_dst2  = (const float*)d_in[11];
    const float* b2      = (const float*)d_in[12];
    float* out = (float*)d_out;

    int n = in_sizes[0] / IND;
    int E = in_sizes[2] / 2;
    int tot = E + n;

    int *p_deg, *p_cursor;
    cudaGetSymbolAddress((void**)&p_deg, g_deg);
    cudaGetSymbolAddress((void**)&p_cursor, g_cursor);
    float *p_h0, *p_h1, *p_o1, *p_h2;
    cudaGetSymbolAddress((void**)&p_h0, g_h0);
    cudaGetSymbolAddress((void**)&p_h1, g_h1);
    cudaGetSymbolAddress((void**)&p_o1, g_o1);
    cudaGetSymbolAddress((void**)&p_h2, g_h2);
    float *p_as1, *p_ad1, *p_as2, *p_ad2;
    cudaGetSymbolAddress((void**)&p_as1, g_as1);
    cudaGetSymbolAddress((void**)&p_ad1, g_ad1);
    cudaGetSymbolAddress((void**)&p_as2, g_as2);
    cudaGetSymbolAddress((void**)&p_ad2, g_ad2);

    // launches 1-5 (CSR front half)
    k_detect<<<1, 1>>>(ei);
    k_prep<<<(tot + 255) / 256, 256>>>(ei, E, n);
    k_filli<<<(n + 255) / 256, 256>>>(p_deg, 0, n);
    k_filli<<<(n + 255) / 256, 256>>>(p_cursor, 0, n);
    k_hist<<<(tot + 255) / 256, 256>>>(tot);

    // launch 6: encoder GEMM with fused rank-2 + bias epilogue (ncu -s 5 lands here)
    {
        dim3 grid(IND / 128, (n + 127) / 128);
        k_gemm<1><<<grid, 256>>>(x, encW, p_h0, n, IND, IND,
                                 na, encW + (size_t)384 * IND, encb,
                                 nullptr, nullptr, 0, 0);
    }

    // CSR back half
    k_scan<<<1, 1024>>>(n);
    k_scatter<<<(tot + 255) / 256, 256>>>(tot);

    // ---- GAT layer 1: GEMM with fused alpha epilogue ----
    k_zero2<<<(n * H1 + 255) / 256, 256>>>(p_as1, p_ad1, n * H1, n * H1);
    {
        dim3 grid(HID1 / 128, (n + 127) / 128);
        k_gemm<2><<<grid, 256>>>(p_h0, W1, p_h1, n, HID1, IND,
                                 a_src1, a_dst1, nullptr,
                                 p_as1, p_ad1, H1, 8);
    }
    k_attn_agg1<<<n, 256>>>(b1);

    // ---- GAT layer 2: GEMM with fused alpha epilogue ----
    k_zero2<<<(n + 255) / 256, 256>>>(p_as2, p_ad2, n, n);
    {
        dim3 grid(C2 / 128, (n + 127) / 128);
        k_gemm<2><<<grid, 256>>>(p_o1, W2, p_h2, n, C2, HID1,
                                 a_src2, a_dst2, nullptr,
                                 p_as2, p_ad2, 1, 7);
    }
    k_attn_agg2<<<n, 128>>>(b2, out);
}